// round 5
// baseline (speedup 1.0000x reference)
#include <cuda_runtime.h>
#include <math.h>

#define FULLM 0xffffffffu

__device__ float g_lse[128];    // [64][2]
__device__ float g_res[3072];   // [1024][3]

__global__ __launch_bounds__(256) void k_lse(const float* __restrict__ F0)
{
    const int b = blockIdx.x;
    const float* F = F0 + (long long)b * 78000;
    const int tid = threadIdx.x, w = tid >> 5, lane = tid & 31;
    float m0 = -3.4e38f, m1 = -3.4e38f;
    for (int i = tid; i < 1000; i += 256) {
        m0 = fmaxf(m0, F[i * 78]);
        m1 = fmaxf(m1, F[i * 78 + 1]);
    }
    for (int o = 16; o; o >>= 1) {
        m0 = fmaxf(m0, __shfl_xor_sync(FULLM, m0, o));
        m1 = fmaxf(m1, __shfl_xor_sync(FULLM, m1, o));
    }
    __shared__ float sm[16];
    if (lane == 0) { sm[w] = m0; sm[w + 8] = m1; }
    __syncthreads();
    float M0 = sm[0], M1 = sm[8];
    for (int j = 1; j < 8; j++) { M0 = fmaxf(M0, sm[j]); M1 = fmaxf(M1, sm[j + 8]); }
    float s0 = 0.0f, s1 = 0.0f;
    for (int i = tid; i < 1000; i += 256) {
        s0 += expf(F[i * 78] - M0);
        s1 += expf(F[i * 78 + 1] - M1);
    }
    for (int o = 16; o; o >>= 1) {
        s0 += __shfl_xor_sync(FULLM, s0, o);
        s1 += __shfl_xor_sync(FULLM, s1, o);
    }
    __syncthreads();
    if (lane == 0) { sm[w] = s0; sm[w + 8] = s1; }
    __syncthreads();
    if (tid == 0) {
        float S0 = 0.0f, S1 = 0.0f;
        for (int j = 0; j < 8; j++) { S0 += sm[j]; S1 += sm[j + 8]; }
        g_lse[b * 2 + 0] = M0 + logf(S0);
        g_lse[b * 2 + 1] = M1 + logf(S1);
    }
}

__global__ __launch_bounds__(256) void k_main(const float* __restrict__ OUT,
                                              const float* __restrict__ LAB)
{
    const int bid = blockIdx.x;
    const int b = bid >> 4;
    const float* F  = OUT + (long long)b * 78000;
    const float* PR = LAB + (long long)bid * 78;

    __shared__ float    sPrior[78];
    __shared__ unsigned sKey[1000];
    __shared__ float    sFoc[1000];
    __shared__ float    sLiou[1000];
    __shared__ float    sRed[48];
    __shared__ float    sB[12];
    __shared__ int      sKk;
    __shared__ int      sC1[8], sC2[8];

    const int tid  = threadIdx.x, w = tid >> 5, lane = tid & 31;
    const int hl   = lane & 15;
    const int half = lane >> 4;
    const int base16 = lane & 16;

    if (tid < 78) sPrior[tid] = PR[tid];
    __syncthreads();

    const float LSE0 = g_lse[b * 2 + 0];
    const float LSE1 = g_lse[b * 2 + 1];
    const float pr0 = sPrior[hl];
    const float pr1 = sPrior[hl + 16];
    const float pr2 = sPrior[hl + 32];
    const float pr3 = sPrior[hl + 48];
    const float pr4 = (hl < 14) ? sPrior[hl + 64] : 0.0f;

    float accD = 0.0f, accX = 0.0f, accT = 0.0f, accL = 0.0f;

    // pass 1: per-row stats, half-warp per row
    for (int i0 = 2 * w; i0 < 1000; i0 += 16) {
        const int i = i0 + half;
        const float* R = F + i * 78;

        float v0 = R[hl];
        float l1 = (hl >= 6) ? fabsf(v0 - pr0) : 0.0f;
        l1 += fabsf(R[hl + 16] - pr1);
        l1 += fabsf(R[hl + 32] - pr2);
        l1 += fabsf(R[hl + 48] - pr3);
        if (hl < 14) l1 += fabsf(R[hl + 64] - pr4);

        float foc = 0.0f, dxy = 0.0f, thv = 0.0f;
        if (hl < 2) {
            float ls = v0 - ((hl == 0) ? LSE0 : LSE1);
            float s  = expf(ls);
            float om = 1.0f - s;
            foc = om * om * ls * pr0;
        } else if (hl == 3 || hl == 4) {
            float d = v0 - pr0;  dxy = d * d;
        } else if (hl == 5) {
            thv = v0 - pr0;
        }

        for (int o = 8; o; o >>= 1) l1 += __shfl_xor_sync(FULLM, l1, o);
        float foct = __shfl_sync(FULLM, foc, base16)     + __shfl_sync(FULLM, foc, base16 + 1);
        float dxyt = __shfl_sync(FULLM, dxy, base16 + 3) + __shfl_sync(FULLM, dxy, base16 + 4);
        float tht  = __shfl_sync(FULLM, thv, base16 + 5);

        if (hl == 0) {
            float dis = l1 * (1.0f / 72.0f);
            float d2  = dis * dis;
            float t2  = tht * tht;
            float P   = d2 * dxyt * t2;
            float liou = 1.0f - (2160.0f - l1) / (2160.0f + l1 + 1e-9f);
            sKey[i]  = __float_as_uint(P);
            sFoc[i]  = foct;
            sLiou[i] = liou;
            accD += d2;  accX += dxyt;  accT += t2;  accL += liou;
        }
    }
    accD += __shfl_xor_sync(FULLM, accD, 16);
    accX += __shfl_xor_sync(FULLM, accX, 16);
    accT += __shfl_xor_sync(FULLM, accT, 16);
    accL += __shfl_xor_sync(FULLM, accL, 16);
    if (lane == 0) { sRed[w*4] = accD; sRed[w*4+1] = accX; sRed[w*4+2] = accT; sRed[w*4+3] = accL; }
    __syncthreads();

    if (tid == 0) {
        float D = 0, X = 0, Tm = 0, L = 0;
        for (int j = 0; j < 8; j++) { D += sRed[j*4]; X += sRed[j*4+1]; Tm += sRed[j*4+2]; L += sRed[j*4+3]; }
        float nd = fmaxf(sqrtf(D),  1e-12f);
        float nx = fmaxf(sqrtf(X),  1e-12f);
        float nt = fmaxf(sqrtf(Tm), 1e-12f);
        float den = nd * nx * nt;
        sB[0] = 3.0f / (den * den);
        int k = (int)L;
        if (k < 1) k = 1;
        if (k > 64) k = 64;
        sKk = k;
    }
    __syncthreads();
    const float cscale = sB[0];
    const int   k      = sKk;

    // cost -> order-preserving uint keys
    int rows[4];
    unsigned kr[4];
    const int nr = (tid < 232) ? 4 : 3;
    for (int r = 0; r < 4; r++) { rows[r] = tid + r * 256; kr[r] = 0xFFFFFFFFu; }
    for (int r = 0; r < nr; r++) {
        int i = rows[r];
        float cost = cscale * __uint_as_float(sKey[i]) + sFoc[i];
        unsigned u = __float_as_uint(cost);
        u = (u & 0x80000000u) ? ~u : (u | 0x80000000u);
        kr[r] = u;
        sKey[i] = u;
    }
    __syncthreads();

    // binary search for k-th smallest key
    unsigned lo = 0u, hi = 0xFFFFFFFFu;
    #pragma unroll 1
    for (int it = 0; it < 32; ++it) {
        unsigned mid = lo + ((hi - lo) >> 1);
        int c = 0;
        for (int r = 0; r < nr; r++) c += (kr[r] <= mid) ? 1 : 0;
        for (int o = 16; o; o >>= 1) c += __shfl_xor_sync(FULLM, c, o);
        if (lane == 0) sC1[w] = c;
        __syncthreads();
        int tot = sC1[0]+sC1[1]+sC1[2]+sC1[3]+sC1[4]+sC1[5]+sC1[6]+sC1[7];
        __syncthreads();
        if (tot >= k) hi = mid; else lo = mid + 1;
    }
    const unsigned Tkey = lo;

    int cl = 0, ce = 0;
    for (int r = 0; r < nr; r++) { cl += (kr[r] < Tkey); ce += (kr[r] == Tkey); }
    for (int o = 16; o; o >>= 1) {
        cl += __shfl_xor_sync(FULLM, cl, o);
        ce += __shfl_xor_sync(FULLM, ce, o);
    }
    if (lane == 0) { sC1[w] = cl; sC2[w] = ce; }
    __syncthreads();
    int CL = 0, CE = 0;
    for (int j = 0; j < 8; j++) { CL += sC1[j]; CE += sC2[j]; }
    const int  m    = k - CL;
    const bool easy = (CE == m);

    // pass A: select + accumulate col sums, focal, liou over selected rows
    const int tgt = (sPrior[0] >= sPrior[1]) ? 0 : 1;
    float sq0=0, sq1=0, sq2=0, sq3=0, sfl=0, sll=0;
    bool sel[4] = {false,false,false,false};
    for (int r = 0; r < nr; r++) {
        int i = rows[r];
        bool s;
        if (kr[r] < Tkey) s = true;
        else if (kr[r] == Tkey) {
            if (easy) s = true;
            else {
                int rank = 0;
                for (int j = 0; j < i; j++) rank += (sKey[j] == Tkey) ? 1 : 0;
                s = (rank < m);
            }
        } else s = false;
        sel[r] = s;
        if (s) {
            const float* R = F + i * 78;
            float2 l01 = *reinterpret_cast<const float2*>(R);
            float2 v23 = *reinterpret_cast<const float2*>(R + 2);
            float2 v45 = *reinterpret_cast<const float2*>(R + 4);
            sq0 += v23.x * v23.x;  sq1 += v23.y * v23.y;
            sq2 += v45.x * v45.x;  sq3 += v45.y * v45.y;
            float at = (tgt == 0) ? l01.x : l01.y;
            float ao = (tgt == 0) ? l01.y : l01.x;
            float e  = expf(ao - at);
            float lp = -log1pf(e);
            float pt = expf(lp);
            float om = 1.0f - pt;
            sfl += -om * om * lp;
            sll += sLiou[i];
        }
    }
    for (int o = 16; o; o >>= 1) {
        sq0 += __shfl_xor_sync(FULLM, sq0, o);
        sq1 += __shfl_xor_sync(FULLM, sq1, o);
        sq2 += __shfl_xor_sync(FULLM, sq2, o);
        sq3 += __shfl_xor_sync(FULLM, sq3, o);
        sfl += __shfl_xor_sync(FULLM, sfl, o);
        sll += __shfl_xor_sync(FULLM, sll, o);
    }
    if (lane == 0) {
        float* p = &sRed[w * 6];
        p[0]=sq0; p[1]=sq1; p[2]=sq2; p[3]=sq3; p[4]=sfl; p[5]=sll;
    }
    __syncthreads();
    if (tid == 0) {
        float q0=0,q1=0,q2=0,q3=0,FLs=0,LLs=0;
        for (int j = 0; j < 8; j++) {
            q0 += sRed[j*6];   q1 += sRed[j*6+1]; q2 += sRed[j*6+2];
            q3 += sRed[j*6+3]; FLs += sRed[j*6+4]; LLs += sRed[j*6+5];
        }
        float kf = (float)k;
        float lb0 = sPrior[2], lb1 = sPrior[3], lb2 = sPrior[4], lb3 = sPrior[5];
        float dn0 = fmaxf(sqrtf(q0 + lb0*lb0), 1e-12f);
        float dn1 = fmaxf(sqrtf(q1 + lb1*lb1), 1e-12f);
        float dn2 = fmaxf(sqrtf(q2 + lb2*lb2), 1e-12f);
        float dn3 = fmaxf(sqrtf(q3 + lb3*lb3), 1e-12f);
        sB[1] = 1.0f/dn0; sB[2] = 1.0f/dn1; sB[3] = 1.0f/dn2; sB[4] = 1.0f/dn3;
        sB[5] = lb0/dn0;  sB[6] = lb1/dn1;  sB[7] = lb2/dn2;  sB[8] = lb3/dn3;
        sB[9]  = FLs / kf;
        sB[10] = LLs / kf;
    }
    __syncthreads();

    // pass B: smooth-L1 over selected rows using finalized column norms
    const float i0v = sB[1], i1v = sB[2], i2v = sB[3], i3v = sB[4];
    const float b0v = sB[5], b1v = sB[6], b2v = sB[7], b3v = sB[8];
    float ssl = 0.0f;
    for (int r = 0; r < nr; r++) {
        if (!sel[r]) continue;
        const float* R = F + rows[r] * 78;
        float2 v23 = *reinterpret_cast<const float2*>(R + 2);
        float2 v45 = *reinterpret_cast<const float2*>(R + 4);
        float h = 0.0f, d, ad;
        d = v23.x * i0v - b0v; ad = fabsf(d); h += (ad < 1.0f) ? 0.5f*d*d : ad - 0.5f;
        d = v23.y * i1v - b1v; ad = fabsf(d); h += (ad < 1.0f) ? 0.5f*d*d : ad - 0.5f;
        d = v45.x * i2v - b2v; ad = fabsf(d); h += (ad < 1.0f) ? 0.5f*d*d : ad - 0.5f;
        d = v45.y * i3v - b3v; ad = fabsf(d); h += (ad < 1.0f) ? 0.5f*d*d : ad - 0.5f;
        ssl += 0.25f * h;
    }
    for (int o = 16; o; o >>= 1) ssl += __shfl_xor_sync(FULLM, ssl, o);
    if (lane == 0) sRed[w] = ssl;
    __syncthreads();
    if (tid == 0) {
        float SSL = 0.0f;
        for (int j = 0; j < 8; j++) SSL += sRed[j];
        g_res[bid*3 + 0] = SSL / (float)k;
        g_res[bid*3 + 1] = sB[10];
        g_res[bid*3 + 2] = sB[9];
    }
}

__global__ __launch_bounds__(256) void k_final(float* __restrict__ out)
{
    __shared__ float red[24];
    const int tid = threadIdx.x, w = tid >> 5, lane = tid & 31;
    float a = 0.0f, bb = 0.0f, c = 0.0f;
    for (int i = tid; i < 1024; i += 256) {
        a  += g_res[i*3];
        bb += g_res[i*3+1];
        c  += g_res[i*3+2];
    }
    for (int o = 16; o; o >>= 1) {
        a  += __shfl_xor_sync(FULLM, a,  o);
        bb += __shfl_xor_sync(FULLM, bb, o);
        c  += __shfl_xor_sync(FULLM, c,  o);
    }
    if (lane == 0) { red[w] = a; red[w+8] = bb; red[w+16] = c; }
    __syncthreads();
    if (tid == 0) {
        float A=0,B=0,C=0;
        for (int j = 0; j < 8; j++) { A += red[j]; B += red[j+8]; C += red[j+16]; }
        float sl = A * (1.0f/1024.0f);
        float ll = B * (1.0f/1024.0f);
        float fl = C * (1.0f/1024.0f);
        float loss = (sl > 0.0f ? 0.5f*sl : 0.0f)
                   + (ll > 0.0f ? 2.0f*ll : 0.0f)
                   + (fl > 0.0f ? 2.0f*fl : 0.0f);
        out[0] = loss;
    }
}

extern "C" void kernel_launch(void* const* d_in, const int* in_sizes, int n_in,
                              void* d_out, int out_size)
{
    const float* outp = (const float*)d_in[0];
    const float* lab  = (const float*)d_in[1];
    if (n_in >= 2 && in_sizes[0] == 64*16*78) {   // defensive: metadata order
        outp = (const float*)d_in[1];
        lab  = (const float*)d_in[0];
    }
    k_lse  <<<64,   256>>>(outp);
    k_main <<<1024, 256>>>(outp, lab);
    k_final<<<1,    256>>>((float*)d_out);
}

// round 7
// speedup vs baseline: 2.2565x; 2.2565x over previous
#include <cuda_runtime.h>
#include <math.h>

#define FULLM 0xffffffffu

// Static scratch (no allocations)
__device__ float4 g_stat[1024000];   // [bid=b*16+p][row] -> {l1, dxy2, th, 0}
__device__ float2 g_v01[64000];      // [b][row] -> logits cols 0,1
__device__ float  g_Zp[64][8][2];    // partial sums of exp(v0), exp(v1)
__device__ float  g_res[3072];       // [1024][3]

// ---------------------------------------------------------------------------
// Kernel 1: per-row stats vs all 16 priors.  grid (64 batches, 8 tiles), 128 thr.
// ---------------------------------------------------------------------------
__global__ __launch_bounds__(128) void k_stats(const float* __restrict__ OUT,
                                               const float* __restrict__ LAB)
{
    const int b = blockIdx.x, tile = blockIdx.y;
    const int tid = threadIdx.x;

    __shared__ float sPr[1248];               // 16 priors x 78
    for (int j = tid; j < 1248; j += 128) sPr[j] = LAB[(long long)b * 1248 + j];
    __syncthreads();

    const int r = tile * 125 + tid;
    float e0 = 0.0f, e1 = 0.0f;

    if (tid < 125) {
        const float* R = OUT + (long long)b * 78000 + r * 78;
        float2 v01 = *reinterpret_cast<const float2*>(R);
        float2 v23 = *reinterpret_cast<const float2*>(R + 2);
        float2 v45 = *reinterpret_cast<const float2*>(R + 4);
        e0 = expf(v01.x);
        e1 = expf(v01.y);
        g_v01[b * 1000 + r] = v01;

        float acc[16];
        #pragma unroll
        for (int p = 0; p < 16; p++) acc[p] = 0.0f;

        #pragma unroll 4
        for (int c = 6; c < 78; c += 2) {
            float2 v = *reinterpret_cast<const float2*>(R + c);
            #pragma unroll
            for (int p = 0; p < 16; p++) {
                acc[p] += fabsf(v.x - sPr[p * 78 + c]) + fabsf(v.y - sPr[p * 78 + c + 1]);
            }
        }

        #pragma unroll
        for (int p = 0; p < 16; p++) {
            float dx = v23.y - sPr[p * 78 + 3];
            float dy = v45.x - sPr[p * 78 + 4];
            float4 o;
            o.x = acc[p];                     // L1 over cols 6..77
            o.y = dx * dx + dy * dy;          // dxy^2
            o.z = v45.y - sPr[p * 78 + 5];    // theta diff
            o.w = 0.0f;
            g_stat[(b * 16 + p) * 1000 + r] = o;
        }
    }

    // deterministic block reduce of exp partials
    for (int o = 16; o; o >>= 1) {
        e0 += __shfl_xor_sync(FULLM, e0, o);
        e1 += __shfl_xor_sync(FULLM, e1, o);
    }
    __shared__ float sE[8];
    const int w = tid >> 5, lane = tid & 31;
    if (lane == 0) { sE[w] = e0; sE[w + 4] = e1; }
    __syncthreads();
    if (tid == 0) {
        g_Zp[b][tile][0] = sE[0] + sE[1] + sE[2] + sE[3];
        g_Zp[b][tile][1] = sE[4] + sE[5] + sE[6] + sE[7];
    }
}

// ---------------------------------------------------------------------------
// Kernel 2: per-(batch,lane) cost keys, top-k set selection, masked tails.
// grid = 1024 blocks, 256 threads.
// ---------------------------------------------------------------------------
__global__ __launch_bounds__(256) void k_sel(const float* __restrict__ OUT,
                                             const float* __restrict__ LAB)
{
    const int bid = blockIdx.x;
    const int b = bid >> 4;
    const float* F  = OUT + (long long)b * 78000;
    const float* PR = LAB + (long long)bid * 78;

    __shared__ unsigned sKey[1000];
    __shared__ float sRed[48];
    __shared__ float sB[12];
    __shared__ int   sKk;
    __shared__ int   sC1[8], sC2[8];

    const int tid = threadIdx.x, w = tid >> 5, lane = tid & 31;

    // finish column log-softmax denominators (deterministic fixed-order sum)
    float Z0 = 0.0f, Z1 = 0.0f;
    #pragma unroll
    for (int j = 0; j < 8; j++) { Z0 += g_Zp[b][j][0]; Z1 += g_Zp[b][j][1]; }
    const float lnZ0 = logf(Z0), lnZ1 = logf(Z1);
    const float pr0 = PR[0], pr1 = PR[1];

    int rows[4];
    unsigned kr[4];
    float Pv[4], foc[4], liou[4];
    float2 v01r[4];
    const int nr = (tid < 232) ? 4 : 3;
    #pragma unroll
    for (int r = 0; r < 4; r++) {
        rows[r] = tid + r * 256; kr[r] = 0xFFFFFFFFu;
        Pv[r] = 0.0f; foc[r] = 0.0f; liou[r] = 0.0f;
        v01r[r].x = 0.0f; v01r[r].y = 0.0f;
    }

    float accD = 0.0f, accX = 0.0f, accT = 0.0f, accL = 0.0f;
    #pragma unroll
    for (int r = 0; r < 4; r++) {
        if (r < nr) {
            int i = rows[r];
            float4 st  = g_stat[bid * 1000 + i];
            float2 v01 = g_v01[b * 1000 + i];
            v01r[r] = v01;
            float l1  = st.x;
            float dis = l1 * (1.0f / 72.0f);
            float d2  = dis * dis;
            float t2  = st.z * st.z;
            Pv[r]   = d2 * st.y * t2;
            liou[r] = 1.0f - (2160.0f - l1) / (2160.0f + l1 + 1e-9f);
            float ls0 = v01.x - lnZ0, ls1 = v01.y - lnZ1;
            float s0 = expf(ls0),     s1 = expf(ls1);
            float a0 = (1.0f - s0) * (1.0f - s0) * ls0;
            float a1 = (1.0f - s1) * (1.0f - s1) * ls1;
            foc[r] = a0 * pr0 + a1 * pr1;
            accD += d2; accX += st.y; accT += t2; accL += liou[r];
        }
    }
    for (int o = 16; o; o >>= 1) {
        accD += __shfl_xor_sync(FULLM, accD, o);
        accX += __shfl_xor_sync(FULLM, accX, o);
        accT += __shfl_xor_sync(FULLM, accT, o);
        accL += __shfl_xor_sync(FULLM, accL, o);
    }
    if (lane == 0) { sRed[w*4] = accD; sRed[w*4+1] = accX; sRed[w*4+2] = accT; sRed[w*4+3] = accL; }
    __syncthreads();

    if (tid == 0) {
        float D = 0, X = 0, Tm = 0, L = 0;
        for (int j = 0; j < 8; j++) { D += sRed[j*4]; X += sRed[j*4+1]; Tm += sRed[j*4+2]; L += sRed[j*4+3]; }
        float nd = fmaxf(sqrtf(D),  1e-12f);
        float nx = fmaxf(sqrtf(X),  1e-12f);
        float nt = fmaxf(sqrtf(Tm), 1e-12f);
        float den = nd * nx * nt;
        sB[0] = 3.0f / (den * den);            // W_SIM / (Nd*Nxy*Nth)^2
        int k = (int)L;
        if (k < 1) k = 1;
        if (k > 64) k = 64;
        sKk = k;
    }
    __syncthreads();
    const float cscale = sB[0];
    const int   k      = sKk;

    // cost -> order-preserving uint keys
    #pragma unroll
    for (int r = 0; r < 4; r++) {
        if (r < nr) {
            float cost = cscale * Pv[r] + foc[r];   // W_CLS = 1
            unsigned u = __float_as_uint(cost);
            u = (u & 0x80000000u) ? ~u : (u | 0x80000000u);
            kr[r] = u;
            sKey[rows[r]] = u;
        }
    }
    __syncthreads();

    // binary search for k-th smallest key
    unsigned lo = 0u, hi = 0xFFFFFFFFu;
    #pragma unroll 1
    for (int it = 0; it < 32; ++it) {
        unsigned mid = lo + ((hi - lo) >> 1);
        int c = 0;
        #pragma unroll
        for (int r = 0; r < 4; r++) if (r < nr) c += (kr[r] <= mid) ? 1 : 0;
        for (int o = 16; o; o >>= 1) c += __shfl_xor_sync(FULLM, c, o);
        if (lane == 0) sC1[w] = c;
        __syncthreads();
        int tot = sC1[0]+sC1[1]+sC1[2]+sC1[3]+sC1[4]+sC1[5]+sC1[6]+sC1[7];
        __syncthreads();
        if (tot >= k) hi = mid; else lo = mid + 1;
    }
    const unsigned Tkey = lo;

    int cl = 0, ce = 0;
    #pragma unroll
    for (int r = 0; r < 4; r++) if (r < nr) { cl += (kr[r] < Tkey); ce += (kr[r] == Tkey); }
    for (int o = 16; o; o >>= 1) {
        cl += __shfl_xor_sync(FULLM, cl, o);
        ce += __shfl_xor_sync(FULLM, ce, o);
    }
    if (lane == 0) { sC1[w] = cl; sC2[w] = ce; }
    __syncthreads();
    int CL = 0, CE = 0;
    for (int j = 0; j < 8; j++) { CL += sC1[j]; CE += sC2[j]; }
    const int  m    = k - CL;
    const bool easy = (CE == m);

    // pass A: select + accumulate col sums, focal, liou over selected rows
    const int tgt = (pr0 >= pr1) ? 0 : 1;
    float sq0=0, sq1=0, sq2=0, sq3=0, sfl=0, sll=0;
    bool sel[4] = {false,false,false,false};
    #pragma unroll
    for (int r = 0; r < 4; r++) {
        if (r >= nr) continue;
        int i = rows[r];
        bool s;
        if (kr[r] < Tkey) s = true;
        else if (kr[r] == Tkey) {
            if (easy) s = true;
            else {
                int rank = 0;
                for (int j = 0; j < i; j++) rank += (sKey[j] == Tkey) ? 1 : 0;
                s = (rank < m);
            }
        } else s = false;
        sel[r] = s;
        if (s) {
            const float* R = F + i * 78;
            float2 v23 = *reinterpret_cast<const float2*>(R + 2);
            float2 v45 = *reinterpret_cast<const float2*>(R + 4);
            sq0 += v23.x * v23.x;  sq1 += v23.y * v23.y;
            sq2 += v45.x * v45.x;  sq3 += v45.y * v45.y;
            float at = (tgt == 0) ? v01r[r].x : v01r[r].y;
            float ao = (tgt == 0) ? v01r[r].y : v01r[r].x;
            float e  = expf(ao - at);
            float lp = -log1pf(e);
            float pt = expf(lp);
            float om = 1.0f - pt;
            sfl += -om * om * lp;
            sll += liou[r];
        }
    }
    for (int o = 16; o; o >>= 1) {
        sq0 += __shfl_xor_sync(FULLM, sq0, o);
        sq1 += __shfl_xor_sync(FULLM, sq1, o);
        sq2 += __shfl_xor_sync(FULLM, sq2, o);
        sq3 += __shfl_xor_sync(FULLM, sq3, o);
        sfl += __shfl_xor_sync(FULLM, sfl, o);
        sll += __shfl_xor_sync(FULLM, sll, o);
    }
    if (lane == 0) {
        float* p = &sRed[w * 6];
        p[0]=sq0; p[1]=sq1; p[2]=sq2; p[3]=sq3; p[4]=sfl; p[5]=sll;
    }
    __syncthreads();
    if (tid == 0) {
        float q0=0,q1=0,q2=0,q3=0,FLs=0,LLs=0;
        for (int j = 0; j < 8; j++) {
            q0 += sRed[j*6];   q1 += sRed[j*6+1]; q2 += sRed[j*6+2];
            q3 += sRed[j*6+3]; FLs += sRed[j*6+4]; LLs += sRed[j*6+5];
        }
        float kf = (float)k;
        float lb0 = PR[2], lb1 = PR[3], lb2 = PR[4], lb3 = PR[5];
        float dn0 = fmaxf(sqrtf(q0 + lb0*lb0), 1e-12f);
        float dn1 = fmaxf(sqrtf(q1 + lb1*lb1), 1e-12f);
        float dn2 = fmaxf(sqrtf(q2 + lb2*lb2), 1e-12f);
        float dn3 = fmaxf(sqrtf(q3 + lb3*lb3), 1e-12f);
        sB[1] = 1.0f/dn0; sB[2] = 1.0f/dn1; sB[3] = 1.0f/dn2; sB[4] = 1.0f/dn3;
        sB[5] = lb0/dn0;  sB[6] = lb1/dn1;  sB[7] = lb2/dn2;  sB[8] = lb3/dn3;
        sB[9]  = FLs / kf;
        sB[10] = LLs / kf;
    }
    __syncthreads();

    // pass B: smooth-L1 over selected rows using finalized column norms
    const float i0v = sB[1], i1v = sB[2], i2v = sB[3], i3v = sB[4];
    const float b0v = sB[5], b1v = sB[6], b2v = sB[7], b3v = sB[8];
    float ssl = 0.0f;
    #pragma unroll
    for (int r = 0; r < 4; r++) {
        if (r >= nr || !sel[r]) continue;
        const float* R = F + rows[r] * 78;
        float2 v23 = *reinterpret_cast<const float2*>(R + 2);
        float2 v45 = *reinterpret_cast<const float2*>(R + 4);
        float h = 0.0f, d, ad;
        d = v23.x * i0v - b0v; ad = fabsf(d); h += (ad < 1.0f) ? 0.5f*d*d : ad - 0.5f;
        d = v23.y * i1v - b1v; ad = fabsf(d); h += (ad < 1.0f) ? 0.5f*d*d : ad - 0.5f;
        d = v45.x * i2v - b2v; ad = fabsf(d); h += (ad < 1.0f) ? 0.5f*d*d : ad - 0.5f;
        d = v45.y * i3v - b3v; ad = fabsf(d); h += (ad < 1.0f) ? 0.5f*d*d : ad - 0.5f;
        ssl += 0.25f * h;
    }
    for (int o = 16; o; o >>= 1) ssl += __shfl_xor_sync(FULLM, ssl, o);
    if (lane == 0) sRed[w] = ssl;
    __syncthreads();
    if (tid == 0) {
        float SSL = 0.0f;
        for (int j = 0; j < 8; j++) SSL += sRed[j];
        g_res[bid*3 + 0] = SSL / (float)k;
        g_res[bid*3 + 1] = sB[10];
        g_res[bid*3 + 2] = sB[9];
    }
}

// ---------------------------------------------------------------------------
// Kernel 3: final combine
// ---------------------------------------------------------------------------
__global__ __launch_bounds__(256) void k_final(float* __restrict__ out)
{
    __shared__ float red[24];
    const int tid = threadIdx.x, w = tid >> 5, lane = tid & 31;
    float a = 0.0f, bb = 0.0f, c = 0.0f;
    for (int i = tid; i < 1024; i += 256) {
        a  += g_res[i*3];
        bb += g_res[i*3+1];
        c  += g_res[i*3+2];
    }
    for (int o = 16; o; o >>= 1) {
        a  += __shfl_xor_sync(FULLM, a,  o);
        bb += __shfl_xor_sync(FULLM, bb, o);
        c  += __shfl_xor_sync(FULLM, c,  o);
    }
    if (lane == 0) { red[w] = a; red[w+8] = bb; red[w+16] = c; }
    __syncthreads();
    if (tid == 0) {
        float A=0,B=0,C=0;
        for (int j = 0; j < 8; j++) { A += red[j]; B += red[j+8]; C += red[j+16]; }
        float sl = A * (1.0f/1024.0f);
        float ll = B * (1.0f/1024.0f);
        float fl = C * (1.0f/1024.0f);
        float loss = (sl > 0.0f ? 0.5f*sl : 0.0f)
                   + (ll > 0.0f ? 2.0f*ll : 0.0f)
                   + (fl > 0.0f ? 2.0f*fl : 0.0f);
        out[0] = loss;
    }
}

extern "C" void kernel_launch(void* const* d_in, const int* in_sizes, int n_in,
                              void* d_out, int out_size)
{
    const float* outp = (const float*)d_in[0];
    const float* lab  = (const float*)d_in[1];
    if (n_in >= 2 && in_sizes[0] == 64*16*78) {   // defensive: metadata order
        outp = (const float*)d_in[1];
        lab  = (const float*)d_in[0];
    }
    k_stats<<<dim3(64, 8), 128>>>(outp, lab);
    k_sel  <<<1024, 256>>>(outp, lab);
    k_final<<<1, 256>>>((float*)d_out);
}

// round 8
// speedup vs baseline: 2.5358x; 1.1237x over previous
#include <cuda_runtime.h>
#include <math.h>

#define FULLM 0xffffffffu

// Static scratch (no allocations)
__device__ float4 g_stat[1024000];   // [bid=b*16+p][row] -> {l1, dxy2, th, 0}
__device__ float2 g_v01[64000];      // [b][row] -> logits cols 0,1
__device__ float  g_Zp[64][8][2];    // partial sums of exp(v0), exp(v1)
__device__ float  g_res[3072];       // [1024][3]
__device__ unsigned g_done = 0;      // completion counter (reset each replay)

// ---------------------------------------------------------------------------
// Kernel 1: per-row stats vs priors. blockDim 256 = 128 rows x 2 prior-groups.
// grid (64 batches, 8 tiles of 125 rows).
// ---------------------------------------------------------------------------
__global__ __launch_bounds__(256) void k_stats(const float* __restrict__ OUT,
                                               const float* __restrict__ LAB)
{
    const int b = blockIdx.x, tile = blockIdx.y;
    const int tid = threadIdx.x;
    const int pg  = tid >> 7;          // 0: priors 0-7, 1: priors 8-15
    const int rl  = tid & 127;

    __shared__ float sPr[1248];        // 16 priors x 78
    __shared__ float sE[8];
    for (int j = tid; j < 1248; j += 256) sPr[j] = LAB[(long long)b * 1248 + j];
    __syncthreads();

    const int row = tile * 125 + rl;
    float e0 = 0.0f, e1 = 0.0f;

    if (rl < 125) {
        const float* R = OUT + (long long)b * 78000 + row * 78;
        float2 v01 = *reinterpret_cast<const float2*>(R);
        float2 v23 = *reinterpret_cast<const float2*>(R + 2);
        float2 v45 = *reinterpret_cast<const float2*>(R + 4);
        if (pg == 0) {
            e0 = expf(v01.x);
            e1 = expf(v01.y);
            g_v01[b * 1000 + row] = v01;
        }

        float acc[8];
        #pragma unroll
        for (int j = 0; j < 8; j++) acc[j] = 0.0f;

        const float* P0 = sPr + pg * 8 * 78;
        #pragma unroll 4
        for (int c = 6; c < 78; c += 2) {
            float2 v = *reinterpret_cast<const float2*>(R + c);
            #pragma unroll
            for (int j = 0; j < 8; j++) {
                float2 pv = *reinterpret_cast<const float2*>(P0 + j * 78 + c);
                acc[j] += fabsf(v.x - pv.x) + fabsf(v.y - pv.y);
            }
        }

        #pragma unroll
        for (int j = 0; j < 8; j++) {
            int p = pg * 8 + j;
            float dx = v23.y - sPr[p * 78 + 3];
            float dy = v45.x - sPr[p * 78 + 4];
            float4 o;
            o.x = acc[j];                     // L1 over cols 6..77
            o.y = dx * dx + dy * dy;          // dxy^2
            o.z = v45.y - sPr[p * 78 + 5];    // theta diff
            o.w = 0.0f;
            g_stat[(b * 16 + p) * 1000 + row] = o;
        }
    }

    // Zp partials: only pg0 (warps 0-3) holds e0/e1; inactive lanes carry 0.
    if (pg == 0) {
        for (int o = 16; o; o >>= 1) {
            e0 += __shfl_xor_sync(FULLM, e0, o);
            e1 += __shfl_xor_sync(FULLM, e1, o);
        }
        const int w = tid >> 5, lane = tid & 31;
        if (lane == 0) { sE[w] = e0; sE[w + 4] = e1; }
    }
    __syncthreads();
    if (tid == 0) {
        g_Zp[b][tile][0] = sE[0] + sE[1] + sE[2] + sE[3];
        g_Zp[b][tile][1] = sE[4] + sE[5] + sE[6] + sE[7];
    }
}

// ---------------------------------------------------------------------------
// Kernel 2: per-(batch,lane) cost keys, top-k set selection, masked tails,
// plus folded final reduction (last block). grid = 1024 blocks, 256 threads.
// ---------------------------------------------------------------------------
__global__ __launch_bounds__(256) void k_sel(const float* __restrict__ OUT,
                                             const float* __restrict__ LAB,
                                             float* __restrict__ out)
{
    const int bid = blockIdx.x;
    const int b = bid >> 4;
    const float* F  = OUT + (long long)b * 78000;
    const float* PR = LAB + (long long)bid * 78;

    __shared__ unsigned sKey[1000];
    __shared__ float sRed[48];
    __shared__ float sB[12];
    __shared__ int   sKk;
    __shared__ int   sC[2][8];
    __shared__ int   sC1[8], sC2[8];
    __shared__ bool  sLast;

    const int tid = threadIdx.x, w = tid >> 5, lane = tid & 31;

    // finish column log-softmax denominators (deterministic fixed-order sum)
    float Z0 = 0.0f, Z1 = 0.0f;
    #pragma unroll
    for (int j = 0; j < 8; j++) { Z0 += g_Zp[b][j][0]; Z1 += g_Zp[b][j][1]; }
    const float lnZ0 = logf(Z0), lnZ1 = logf(Z1);
    const float pr0 = PR[0], pr1 = PR[1];

    int rows[4];
    unsigned kr[4];
    float Pv[4], foc[4], liou[4];
    float2 v01r[4];
    const int nr = (tid < 232) ? 4 : 3;
    #pragma unroll
    for (int r = 0; r < 4; r++) {
        rows[r] = tid + r * 256; kr[r] = 0xFFFFFFFFu;
        Pv[r] = 0.0f; foc[r] = 0.0f; liou[r] = 0.0f;
        v01r[r].x = 0.0f; v01r[r].y = 0.0f;
    }

    float accD = 0.0f, accX = 0.0f, accT = 0.0f, accL = 0.0f;
    #pragma unroll
    for (int r = 0; r < 4; r++) {
        if (r < nr) {
            int i = rows[r];
            float4 st  = g_stat[bid * 1000 + i];
            float2 v01 = g_v01[b * 1000 + i];
            v01r[r] = v01;
            float l1  = st.x;
            float dis = l1 * (1.0f / 72.0f);
            float d2  = dis * dis;
            float t2  = st.z * st.z;
            Pv[r]   = d2 * st.y * t2;
            liou[r] = 1.0f - (2160.0f - l1) / (2160.0f + l1 + 1e-9f);
            float ls0 = v01.x - lnZ0, ls1 = v01.y - lnZ1;
            float s0 = expf(ls0),     s1 = expf(ls1);
            float a0 = (1.0f - s0) * (1.0f - s0) * ls0;
            float a1 = (1.0f - s1) * (1.0f - s1) * ls1;
            foc[r] = a0 * pr0 + a1 * pr1;
            accD += d2; accX += st.y; accT += t2; accL += liou[r];
        }
    }
    for (int o = 16; o; o >>= 1) {
        accD += __shfl_xor_sync(FULLM, accD, o);
        accX += __shfl_xor_sync(FULLM, accX, o);
        accT += __shfl_xor_sync(FULLM, accT, o);
        accL += __shfl_xor_sync(FULLM, accL, o);
    }
    if (lane == 0) { sRed[w*4] = accD; sRed[w*4+1] = accX; sRed[w*4+2] = accT; sRed[w*4+3] = accL; }
    __syncthreads();

    if (tid == 0) {
        float D = 0, X = 0, Tm = 0, L = 0;
        for (int j = 0; j < 8; j++) { D += sRed[j*4]; X += sRed[j*4+1]; Tm += sRed[j*4+2]; L += sRed[j*4+3]; }
        float nd = fmaxf(sqrtf(D),  1e-12f);
        float nx = fmaxf(sqrtf(X),  1e-12f);
        float nt = fmaxf(sqrtf(Tm), 1e-12f);
        float den = nd * nx * nt;
        sB[0] = 3.0f / (den * den);            // W_SIM / (Nd*Nxy*Nth)^2
        int k = (int)L;
        if (k < 1) k = 1;
        if (k > 64) k = 64;
        sKk = k;
    }
    __syncthreads();
    const float cscale = sB[0];
    const int   k      = sKk;

    // cost -> order-preserving uint keys
    #pragma unroll
    for (int r = 0; r < 4; r++) {
        if (r < nr) {
            float cost = cscale * Pv[r] + foc[r];   // W_CLS = 1
            unsigned u = __float_as_uint(cost);
            u = (u & 0x80000000u) ? ~u : (u | 0x80000000u);
            kr[r] = u;
            sKey[rows[r]] = u;
        }
    }
    __syncthreads();

    // binary search for k-th smallest key: 1 barrier/iter, REDUX warp reduce,
    // double-buffered count slots (racing writes go to the other buffer).
    unsigned lo = 0u, hi = 0xFFFFFFFFu;
    #pragma unroll 1
    for (int it = 0; it < 32; ++it) {
        const int buf = it & 1;
        unsigned mid = lo + ((hi - lo) >> 1);
        int c = 0;
        #pragma unroll
        for (int r = 0; r < 4; r++) if (r < nr) c += (kr[r] <= mid) ? 1 : 0;
        c = __reduce_add_sync(FULLM, c);
        if (lane == 0) sC[buf][w] = c;
        __syncthreads();
        int tot = sC[buf][0]+sC[buf][1]+sC[buf][2]+sC[buf][3]
                + sC[buf][4]+sC[buf][5]+sC[buf][6]+sC[buf][7];
        if (tot >= k) hi = mid; else lo = mid + 1;
    }
    const unsigned Tkey = lo;

    int cl = 0, ce = 0;
    #pragma unroll
    for (int r = 0; r < 4; r++) if (r < nr) { cl += (kr[r] < Tkey); ce += (kr[r] == Tkey); }
    cl = __reduce_add_sync(FULLM, cl);
    ce = __reduce_add_sync(FULLM, ce);
    if (lane == 0) { sC1[w] = cl; sC2[w] = ce; }
    __syncthreads();
    int CL = 0, CE = 0;
    for (int j = 0; j < 8; j++) { CL += sC1[j]; CE += sC2[j]; }
    const int  m    = k - CL;
    const bool easy = (CE == m);

    // pass A: select + accumulate col sums, focal, liou over selected rows
    const int tgt = (pr0 >= pr1) ? 0 : 1;
    float sq0=0, sq1=0, sq2=0, sq3=0, sfl=0, sll=0;
    bool sel[4] = {false,false,false,false};
    #pragma unroll
    for (int r = 0; r < 4; r++) {
        if (r >= nr) continue;
        int i = rows[r];
        bool s;
        if (kr[r] < Tkey) s = true;
        else if (kr[r] == Tkey) {
            if (easy) s = true;
            else {
                int rank = 0;
                for (int j = 0; j < i; j++) rank += (sKey[j] == Tkey) ? 1 : 0;
                s = (rank < m);
            }
        } else s = false;
        sel[r] = s;
        if (s) {
            const float* R = F + i * 78;
            float2 v23 = *reinterpret_cast<const float2*>(R + 2);
            float2 v45 = *reinterpret_cast<const float2*>(R + 4);
            sq0 += v23.x * v23.x;  sq1 += v23.y * v23.y;
            sq2 += v45.x * v45.x;  sq3 += v45.y * v45.y;
            float at = (tgt == 0) ? v01r[r].x : v01r[r].y;
            float ao = (tgt == 0) ? v01r[r].y : v01r[r].x;
            float e  = expf(ao - at);
            float lp = -log1pf(e);
            float pt = expf(lp);
            float om = 1.0f - pt;
            sfl += -om * om * lp;
            sll += liou[r];
        }
    }
    for (int o = 16; o; o >>= 1) {
        sq0 += __shfl_xor_sync(FULLM, sq0, o);
        sq1 += __shfl_xor_sync(FULLM, sq1, o);
        sq2 += __shfl_xor_sync(FULLM, sq2, o);
        sq3 += __shfl_xor_sync(FULLM, sq3, o);
        sfl += __shfl_xor_sync(FULLM, sfl, o);
        sll += __shfl_xor_sync(FULLM, sll, o);
    }
    if (lane == 0) {
        float* p = &sRed[w * 6];
        p[0]=sq0; p[1]=sq1; p[2]=sq2; p[3]=sq3; p[4]=sfl; p[5]=sll;
    }
    __syncthreads();
    if (tid == 0) {
        float q0=0,q1=0,q2=0,q3=0,FLs=0,LLs=0;
        for (int j = 0; j < 8; j++) {
            q0 += sRed[j*6];   q1 += sRed[j*6+1]; q2 += sRed[j*6+2];
            q3 += sRed[j*6+3]; FLs += sRed[j*6+4]; LLs += sRed[j*6+5];
        }
        float kf = (float)k;
        float lb0 = PR[2], lb1 = PR[3], lb2 = PR[4], lb3 = PR[5];
        float dn0 = fmaxf(sqrtf(q0 + lb0*lb0), 1e-12f);
        float dn1 = fmaxf(sqrtf(q1 + lb1*lb1), 1e-12f);
        float dn2 = fmaxf(sqrtf(q2 + lb2*lb2), 1e-12f);
        float dn3 = fmaxf(sqrtf(q3 + lb3*lb3), 1e-12f);
        sB[1] = 1.0f/dn0; sB[2] = 1.0f/dn1; sB[3] = 1.0f/dn2; sB[4] = 1.0f/dn3;
        sB[5] = lb0/dn0;  sB[6] = lb1/dn1;  sB[7] = lb2/dn2;  sB[8] = lb3/dn3;
        sB[9]  = FLs / kf;
        sB[10] = LLs / kf;
    }
    __syncthreads();

    // pass B: smooth-L1 over selected rows using finalized column norms
    const float i0v = sB[1], i1v = sB[2], i2v = sB[3], i3v = sB[4];
    const float b0v = sB[5], b1v = sB[6], b2v = sB[7], b3v = sB[8];
    float ssl = 0.0f;
    #pragma unroll
    for (int r = 0; r < 4; r++) {
        if (r >= nr || !sel[r]) continue;
        const float* R = F + rows[r] * 78;
        float2 v23 = *reinterpret_cast<const float2*>(R + 2);
        float2 v45 = *reinterpret_cast<const float2*>(R + 4);
        float h = 0.0f, d, ad;
        d = v23.x * i0v - b0v; ad = fabsf(d); h += (ad < 1.0f) ? 0.5f*d*d : ad - 0.5f;
        d = v23.y * i1v - b1v; ad = fabsf(d); h += (ad < 1.0f) ? 0.5f*d*d : ad - 0.5f;
        d = v45.x * i2v - b2v; ad = fabsf(d); h += (ad < 1.0f) ? 0.5f*d*d : ad - 0.5f;
        d = v45.y * i3v - b3v; ad = fabsf(d); h += (ad < 1.0f) ? 0.5f*d*d : ad - 0.5f;
        ssl += 0.25f * h;
    }
    for (int o = 16; o; o >>= 1) ssl += __shfl_xor_sync(FULLM, ssl, o);
    if (lane == 0) sRed[w] = ssl;
    __syncthreads();
    if (tid == 0) {
        float SSL = 0.0f;
        for (int j = 0; j < 8; j++) SSL += sRed[j];
        g_res[bid*3 + 0] = SSL / (float)k;
        g_res[bid*3 + 1] = sB[10];
        g_res[bid*3 + 2] = sB[9];
    }
    __syncthreads();

    // ---- folded final reduction: last block to finish does the combine ----
    __threadfence();
    if (tid == 0) {
        unsigned t = atomicAdd(&g_done, 1u);
        sLast = (t == (unsigned)(gridDim.x - 1));
    }
    __syncthreads();
    if (!sLast) return;
    __threadfence();

    float a = 0.0f, bb = 0.0f, cc = 0.0f;
    for (int i = tid; i < 1024; i += 256) {
        a  += g_res[i*3];
        bb += g_res[i*3+1];
        cc += g_res[i*3+2];
    }
    for (int o = 16; o; o >>= 1) {
        a  += __shfl_xor_sync(FULLM, a,  o);
        bb += __shfl_xor_sync(FULLM, bb, o);
        cc += __shfl_xor_sync(FULLM, cc, o);
    }
    if (lane == 0) { sRed[w] = a; sRed[w+8] = bb; sRed[w+16] = cc; }
    __syncthreads();
    if (tid == 0) {
        float A=0,B=0,C=0;
        for (int j = 0; j < 8; j++) { A += sRed[j]; B += sRed[j+8]; C += sRed[j+16]; }
        float sl = A * (1.0f/1024.0f);
        float ll = B * (1.0f/1024.0f);
        float fl = C * (1.0f/1024.0f);
        float loss = (sl > 0.0f ? 0.5f*sl : 0.0f)
                   + (ll > 0.0f ? 2.0f*ll : 0.0f)
                   + (fl > 0.0f ? 2.0f*fl : 0.0f);
        out[0] = loss;
        g_done = 0;                      // reset for next graph replay
    }
}

extern "C" void kernel_launch(void* const* d_in, const int* in_sizes, int n_in,
                              void* d_out, int out_size)
{
    const float* outp = (const float*)d_in[0];
    const float* lab  = (const float*)d_in[1];
    if (n_in >= 2 && in_sizes[0] == 64*16*78) {   // defensive: metadata order
        outp = (const float*)d_in[1];
        lab  = (const float*)d_in[0];
    }
    k_stats<<<dim3(64, 8), 256>>>(outp, lab);
    k_sel  <<<1024, 256>>>(outp, lab, (float*)d_out);
}

// round 9
// speedup vs baseline: 3.2264x; 1.2723x over previous
#include <cuda_runtime.h>
#include <math.h>

#define FULLM 0xffffffffu

// Static scratch (no allocations)
__device__ float4 g_stat[1024000];   // [bid=b*16+p][row] -> {l1, dxy2, th, 0}
__device__ float4 g_v01e[64000];     // [b][row] -> {v0, v1, exp(v0), exp(v1)}
__device__ float  g_Zp[64][8][2];    // partial sums of exp(v0), exp(v1)
__device__ float  g_res[3072];       // [1024][3]
__device__ unsigned g_done = 0;      // completion counter (reset each replay)

// ---------------------------------------------------------------------------
// Kernel 1: per-row stats vs priors. blockDim 256 = 128 rows x 2 prior-groups.
// grid (64 batches, 8 tiles of 125 rows).
// ---------------------------------------------------------------------------
__global__ __launch_bounds__(256) void k_stats(const float* __restrict__ OUT,
                                               const float* __restrict__ LAB)
{
    const int b = blockIdx.x, tile = blockIdx.y;
    const int tid = threadIdx.x;
    const int pg  = tid >> 7;          // 0: priors 0-7, 1: priors 8-15
    const int rl  = tid & 127;

    __shared__ float sPr[1248];        // 16 priors x 78
    __shared__ float sE[8];
    for (int j = tid; j < 1248; j += 256) sPr[j] = LAB[(long long)b * 1248 + j];
    __syncthreads();

    const int row = tile * 125 + rl;
    float e0 = 0.0f, e1 = 0.0f;

    if (rl < 125) {
        const float* R = OUT + (long long)b * 78000 + row * 78;
        float2 v01 = *reinterpret_cast<const float2*>(R);
        float2 v23 = *reinterpret_cast<const float2*>(R + 2);
        float2 v45 = *reinterpret_cast<const float2*>(R + 4);
        if (pg == 0) {
            e0 = expf(v01.x);
            e1 = expf(v01.y);
            g_v01e[b * 1000 + row] = make_float4(v01.x, v01.y, e0, e1);
        }

        float acc[8];
        #pragma unroll
        for (int j = 0; j < 8; j++) acc[j] = 0.0f;

        const float* P0 = sPr + pg * 8 * 78;
        #pragma unroll 4
        for (int c = 6; c < 78; c += 2) {
            float2 v = *reinterpret_cast<const float2*>(R + c);
            #pragma unroll
            for (int j = 0; j < 8; j++) {
                float2 pv = *reinterpret_cast<const float2*>(P0 + j * 78 + c);
                acc[j] += fabsf(v.x - pv.x) + fabsf(v.y - pv.y);
            }
        }

        #pragma unroll
        for (int j = 0; j < 8; j++) {
            int p = pg * 8 + j;
            float dx = v23.y - sPr[p * 78 + 3];
            float dy = v45.x - sPr[p * 78 + 4];
            float4 o;
            o.x = acc[j];                     // L1 over cols 6..77
            o.y = dx * dx + dy * dy;          // dxy^2
            o.z = v45.y - sPr[p * 78 + 5];    // theta diff
            o.w = 0.0f;
            g_stat[(b * 16 + p) * 1000 + row] = o;
        }
    }

    if (pg == 0) {
        for (int o = 16; o; o >>= 1) {
            e0 += __shfl_xor_sync(FULLM, e0, o);
            e1 += __shfl_xor_sync(FULLM, e1, o);
        }
        const int w = tid >> 5, lane = tid & 31;
        if (lane == 0) { sE[w] = e0; sE[w + 4] = e1; }
    }
    __syncthreads();
    if (tid == 0) {
        g_Zp[b][tile][0] = sE[0] + sE[1] + sE[2] + sE[3];
        g_Zp[b][tile][1] = sE[4] + sE[5] + sE[6] + sE[7];
    }
}

// ---------------------------------------------------------------------------
// Kernel 2: per-(batch,lane) cost keys, 4-pass radix top-k set selection,
// masked tails, folded final reduce. grid = 1024 blocks, 128 threads.
// ---------------------------------------------------------------------------
__global__ __launch_bounds__(128) void k_sel(const float* __restrict__ OUT,
                                             const float* __restrict__ LAB,
                                             float* __restrict__ out)
{
    const int bid = blockIdx.x;
    const int b = bid >> 4;
    const float* F  = OUT + (long long)b * 78000;
    const float* PR = LAB + (long long)bid * 78;

    __shared__ unsigned sKey[1000];    // Pv bits, then transformed keys
    __shared__ float    sFoc[1000];
    __shared__ int      sHist[2][256];
    __shared__ float    sRed[32];
    __shared__ float    sB[12];
    __shared__ int      sKk;
    __shared__ unsigned sPfxS;
    __shared__ int      sKkS, sCLS, sCES;
    __shared__ bool     sLast;

    const int tid = threadIdx.x, w = tid >> 5, lane = tid & 31;

    // softmax denominators (deterministic fixed-order sum)
    float Z0 = 0.0f, Z1 = 0.0f;
    #pragma unroll
    for (int j = 0; j < 8; j++) { Z0 += g_Zp[b][j][0]; Z1 += g_Zp[b][j][1]; }
    const float lnZ0 = logf(Z0), lnZ1 = logf(Z1);
    const float iZ0 = 1.0f / Z0, iZ1 = 1.0f / Z1;
    const float pr0 = PR[0], pr1 = PR[1];

    const int nr = (tid < 104) ? 8 : 7;     // 104*8 + 24*7 = 1000

    // phase 1: per-key ingredients + block sums
    float accD = 0.0f, accX = 0.0f, accT = 0.0f, accL = 0.0f;
    #pragma unroll
    for (int rr = 0; rr < 8; rr++) {
        if (rr < nr) {
            int i = tid + rr * 128;
            float4 st = g_stat[bid * 1000 + i];
            float4 ve = g_v01e[b * 1000 + i];
            float l1  = st.x;
            float dis = l1 * (1.0f / 72.0f);
            float d2  = dis * dis;
            float t2  = st.z * st.z;
            float Pv  = d2 * st.y * t2;
            float liou = 1.0f - (2160.0f - l1) / (2160.0f + l1 + 1e-9f);
            float ls0 = ve.x - lnZ0, ls1 = ve.y - lnZ1;
            float s0  = ve.z * iZ0,  s1  = ve.w * iZ1;
            float a0 = (1.0f - s0) * (1.0f - s0) * ls0;
            float a1 = (1.0f - s1) * (1.0f - s1) * ls1;
            sKey[i] = __float_as_uint(Pv);
            sFoc[i] = a0 * pr0 + a1 * pr1;
            accD += d2; accX += st.y; accT += t2; accL += liou;
        }
    }
    for (int o = 16; o; o >>= 1) {
        accD += __shfl_xor_sync(FULLM, accD, o);
        accX += __shfl_xor_sync(FULLM, accX, o);
        accT += __shfl_xor_sync(FULLM, accT, o);
        accL += __shfl_xor_sync(FULLM, accL, o);
    }
    if (lane == 0) { sRed[w*4] = accD; sRed[w*4+1] = accX; sRed[w*4+2] = accT; sRed[w*4+3] = accL; }
    // zero both radix histograms while reductions settle
    #pragma unroll
    for (int j = 0; j < 4; j++) ((int*)sHist)[tid + j * 128] = 0;
    __syncthreads();

    if (tid == 0) {
        float D = 0, X = 0, Tm = 0, L = 0;
        for (int j = 0; j < 4; j++) { D += sRed[j*4]; X += sRed[j*4+1]; Tm += sRed[j*4+2]; L += sRed[j*4+3]; }
        float nd = fmaxf(sqrtf(D),  1e-12f);
        float nx = fmaxf(sqrtf(X),  1e-12f);
        float nt = fmaxf(sqrtf(Tm), 1e-12f);
        float den = nd * nx * nt;
        sB[0] = 3.0f / (den * den);            // W_SIM / (Nd*Nxy*Nth)^2
        int k = (int)L;
        if (k < 1) k = 1;
        if (k > 64) k = 64;
        sKk = k;
        sPfxS = 0u; sCLS = 0; sKkS = k; sCES = 0;
    }
    __syncthreads();
    const float cscale = sB[0];
    const int   k      = sKk;

    // cost -> order-preserving uint keys (registers + smem copy for tie ranks)
    unsigned kr[8];
    #pragma unroll
    for (int rr = 0; rr < 8; rr++) {
        kr[rr] = 0xFFFFFFFFu;
        if (rr < nr) {
            int i = tid + rr * 128;
            float cost = cscale * __uint_as_float(sKey[i]) + sFoc[i];  // W_CLS = 1
            unsigned u = __float_as_uint(cost);
            u = (u & 0x80000000u) ? ~u : (u | 0x80000000u);
            kr[rr] = u;
            sKey[i] = u;
        }
    }
    __syncthreads();

    // 4-pass radix select (MSB first): exact k-th smallest key + CL/CE
    #pragma unroll
    for (int p = 0; p < 4; p++) {
        const int shift = 24 - 8 * p;
        const int buf = p & 1;
        const unsigned pfx = sPfxS;
        #pragma unroll
        for (int rr = 0; rr < 8; rr++) {
            if (rr < nr) {
                bool match = (p == 0) || (((kr[rr] ^ pfx) >> (shift + 8)) == 0u);
                if (match) atomicAdd(&sHist[buf][(kr[rr] >> shift) & 255u], 1);
            }
        }
        __syncthreads();
        if (w == 0) {
            int hv[8]; int local = 0;
            #pragma unroll
            for (int j = 0; j < 8; j++) { hv[j] = sHist[buf][lane * 8 + j]; local += hv[j]; }
            int inc = local;
            #pragma unroll
            for (int o = 1; o < 32; o <<= 1) {
                int t = __shfl_up_sync(FULLM, inc, o);
                if (lane >= o) inc += t;
            }
            const int cumb = inc - local;
            const int kk = sKkS;
            unsigned ball = __ballot_sync(FULLM, inc >= kk);
            int sel_lane = __ffs(ball) - 1;
            if (lane == sel_lane) {
                int run = cumb;
                #pragma unroll
                for (int j = 0; j < 8; j++) {
                    int h = hv[j];
                    if (run + h >= kk) {
                        sPfxS = pfx | ((unsigned)(lane * 8 + j) << shift);
                        sKkS  = kk - run;
                        sCLS += run;
                        sCES  = h;
                        break;
                    }
                    run += h;
                }
            }
        } else {
            // zero the other buffer for the next pass
            for (int j = tid - 32; j < 256; j += 96) sHist[buf ^ 1][j] = 0;
        }
        __syncthreads();
    }
    const unsigned Tkey = sPfxS;
    const int CL = sCLS, CE = sCES;
    const int  m    = k - CL;
    const bool easy = (CE == m);

    // pass A: select + accumulate col sums, focal, liou over selected rows
    const int tgt = (pr0 >= pr1) ? 0 : 1;
    float sq0=0, sq1=0, sq2=0, sq3=0, sfl=0, sll=0;
    int selMask = 0;
    #pragma unroll
    for (int rr = 0; rr < 8; rr++) {
        if (rr >= nr) continue;
        int i = tid + rr * 128;
        bool s;
        if (kr[rr] < Tkey) s = true;
        else if (kr[rr] == Tkey) {
            if (easy) s = true;
            else {
                int rank = 0;
                for (int j = 0; j < i; j++) rank += (sKey[j] == Tkey) ? 1 : 0;
                s = (rank < m);
            }
        } else s = false;
        if (s) {
            selMask |= (1 << rr);
            const float* R = F + i * 78;
            float2 v23 = *reinterpret_cast<const float2*>(R + 2);
            float2 v45 = *reinterpret_cast<const float2*>(R + 4);
            sq0 += v23.x * v23.x;  sq1 += v23.y * v23.y;
            sq2 += v45.x * v45.x;  sq3 += v45.y * v45.y;
            float4 ve = g_v01e[b * 1000 + i];
            float at = (tgt == 0) ? ve.x : ve.y;
            float ao = (tgt == 0) ? ve.y : ve.x;
            float e  = expf(ao - at);
            float lp = -log1pf(e);
            float pt = expf(lp);
            float om = 1.0f - pt;
            sfl += -om * om * lp;
            float l1 = g_stat[bid * 1000 + i].x;
            sll += 1.0f - (2160.0f - l1) / (2160.0f + l1 + 1e-9f);
        }
    }
    for (int o = 16; o; o >>= 1) {
        sq0 += __shfl_xor_sync(FULLM, sq0, o);
        sq1 += __shfl_xor_sync(FULLM, sq1, o);
        sq2 += __shfl_xor_sync(FULLM, sq2, o);
        sq3 += __shfl_xor_sync(FULLM, sq3, o);
        sfl += __shfl_xor_sync(FULLM, sfl, o);
        sll += __shfl_xor_sync(FULLM, sll, o);
    }
    if (lane == 0) {
        float* p2 = &sRed[w * 6];
        p2[0]=sq0; p2[1]=sq1; p2[2]=sq2; p2[3]=sq3; p2[4]=sfl; p2[5]=sll;
    }
    __syncthreads();
    if (tid == 0) {
        float q0=0,q1=0,q2=0,q3=0,FLs=0,LLs=0;
        for (int j = 0; j < 4; j++) {
            q0 += sRed[j*6];   q1 += sRed[j*6+1]; q2 += sRed[j*6+2];
            q3 += sRed[j*6+3]; FLs += sRed[j*6+4]; LLs += sRed[j*6+5];
        }
        float kf = (float)k;
        float lb0 = PR[2], lb1 = PR[3], lb2 = PR[4], lb3 = PR[5];
        float dn0 = fmaxf(sqrtf(q0 + lb0*lb0), 1e-12f);
        float dn1 = fmaxf(sqrtf(q1 + lb1*lb1), 1e-12f);
        float dn2 = fmaxf(sqrtf(q2 + lb2*lb2), 1e-12f);
        float dn3 = fmaxf(sqrtf(q3 + lb3*lb3), 1e-12f);
        sB[1] = 1.0f/dn0; sB[2] = 1.0f/dn1; sB[3] = 1.0f/dn2; sB[4] = 1.0f/dn3;
        sB[5] = lb0/dn0;  sB[6] = lb1/dn1;  sB[7] = lb2/dn2;  sB[8] = lb3/dn3;
        sB[9]  = FLs / kf;
        sB[10] = LLs / kf;
    }
    __syncthreads();

    // pass B: smooth-L1 over selected rows using finalized column norms
    const float i0v = sB[1], i1v = sB[2], i2v = sB[3], i3v = sB[4];
    const float b0v = sB[5], b1v = sB[6], b2v = sB[7], b3v = sB[8];
    float ssl = 0.0f;
    #pragma unroll
    for (int rr = 0; rr < 8; rr++) {
        if (!(selMask & (1 << rr))) continue;
        const float* R = F + (tid + rr * 128) * 78;
        float2 v23 = *reinterpret_cast<const float2*>(R + 2);
        float2 v45 = *reinterpret_cast<const float2*>(R + 4);
        float h = 0.0f, d, ad;
        d = v23.x * i0v - b0v; ad = fabsf(d); h += (ad < 1.0f) ? 0.5f*d*d : ad - 0.5f;
        d = v23.y * i1v - b1v; ad = fabsf(d); h += (ad < 1.0f) ? 0.5f*d*d : ad - 0.5f;
        d = v45.x * i2v - b2v; ad = fabsf(d); h += (ad < 1.0f) ? 0.5f*d*d : ad - 0.5f;
        d = v45.y * i3v - b3v; ad = fabsf(d); h += (ad < 1.0f) ? 0.5f*d*d : ad - 0.5f;
        ssl += 0.25f * h;
    }
    for (int o = 16; o; o >>= 1) ssl += __shfl_xor_sync(FULLM, ssl, o);
    if (lane == 0) sRed[w] = ssl;
    __syncthreads();
    if (tid == 0) {
        float SSL = sRed[0] + sRed[1] + sRed[2] + sRed[3];
        g_res[bid*3 + 0] = SSL / (float)k;
        g_res[bid*3 + 1] = sB[10];
        g_res[bid*3 + 2] = sB[9];
    }
    __syncthreads();

    // ---- folded final reduction: last block to finish combines everything ---
    __threadfence();
    if (tid == 0) {
        unsigned t = atomicAdd(&g_done, 1u);
        sLast = (t == (unsigned)(gridDim.x - 1));
    }
    __syncthreads();
    if (!sLast) return;
    __threadfence();

    float a = 0.0f, bb = 0.0f, cc = 0.0f;
    for (int i = tid; i < 1024; i += 128) {
        a  += g_res[i*3];
        bb += g_res[i*3+1];
        cc += g_res[i*3+2];
    }
    for (int o = 16; o; o >>= 1) {
        a  += __shfl_xor_sync(FULLM, a,  o);
        bb += __shfl_xor_sync(FULLM, bb, o);
        cc += __shfl_xor_sync(FULLM, cc, o);
    }
    if (lane == 0) { sRed[w] = a; sRed[w+8] = bb; sRed[w+16] = cc; }
    __syncthreads();
    if (tid == 0) {
        float A = sRed[0]+sRed[1]+sRed[2]+sRed[3];
        float B = sRed[8]+sRed[9]+sRed[10]+sRed[11];
        float C = sRed[16]+sRed[17]+sRed[18]+sRed[19];
        float sl = A * (1.0f/1024.0f);
        float ll = B * (1.0f/1024.0f);
        float fl = C * (1.0f/1024.0f);
        float loss = (sl > 0.0f ? 0.5f*sl : 0.0f)
                   + (ll > 0.0f ? 2.0f*ll : 0.0f)
                   + (fl > 0.0f ? 2.0f*fl : 0.0f);
        out[0] = loss;
        g_done = 0;                      // reset for next graph replay
    }
}

extern "C" void kernel_launch(void* const* d_in, const int* in_sizes, int n_in,
                              void* d_out, int out_size)
{
    const float* outp = (const float*)d_in[0];
    const float* lab  = (const float*)d_in[1];
    if (n_in >= 2 && in_sizes[0] == 64*16*78) {   // defensive: metadata order
        outp = (const float*)d_in[1];
        lab  = (const float*)d_in[0];
    }
    k_stats<<<dim3(64, 8), 256>>>(outp, lab);
    k_sel  <<<1024, 128>>>(outp, lab, (float*)d_out);
}

// round 12
// speedup vs baseline: 3.4339x; 1.0643x over previous
#include <cuda_runtime.h>
#include <math.h>

#define FULLM 0xffffffffu

// Static scratch (no allocations)
__device__ float2 g_PL[1024000];     // [bid=b*16+p][row] -> {Pv=(dis*xy*th)^2 raw, l1}
__device__ float4 g_psum[8192];      // [bid][tile] -> {sum d2, sum dxy2, sum t2, sum liou}
__device__ float4 g_v01e[64000];     // [b][row] -> {v0, v1, exp(v0), exp(v1)}
__device__ float  g_Zp[64][8][2];    // partial sums of exp(v0), exp(v1)
__device__ float  g_res[3072];       // [1024][3]
__device__ unsigned g_done = 0;      // completion counter (reset each replay)

// ---------------------------------------------------------------------------
// Kernel 1: per-row stats vs priors + per-tile prior sums.
// blockDim 256 = 128 rows x 2 prior-groups. grid (64 batches, 8 tiles of 125).
// ---------------------------------------------------------------------------
__global__ __launch_bounds__(256) void k_stats(const float* __restrict__ OUT,
                                               const float* __restrict__ LAB)
{
    const int b = blockIdx.x, tile = blockIdx.y;
    const int tid = threadIdx.x;
    const int pg  = tid >> 7;          // 0: priors 0-7, 1: priors 8-15
    const int rl  = tid & 127;
    const int w = tid >> 5, lane = tid & 31;

    __shared__ float sPr[1248];        // 16 priors x 78
    __shared__ float sE[8];
    __shared__ float sW[8][32];        // per-warp partials [warp][j*4+c]
    for (int j = tid; j < 1248; j += 256) sPr[j] = LAB[(long long)b * 1248 + j];
    __syncthreads();

    const int row = tile * 125 + rl;
    const bool act = (rl < 125);
    float e0 = 0.0f, e1 = 0.0f;
    float acc[8];
    float2 v23, v45;

    const float* R = OUT + (long long)b * 78000 + row * 78;
    const float* P0 = sPr + pg * 8 * 78;

    if (act) {
        float2 v01 = *reinterpret_cast<const float2*>(R);
        v23 = *reinterpret_cast<const float2*>(R + 2);
        v45 = *reinterpret_cast<const float2*>(R + 4);
        if (pg == 0) {
            e0 = expf(v01.x);
            e1 = expf(v01.y);
            g_v01e[b * 1000 + row] = make_float4(v01.x, v01.y, e0, e1);
        }
        #pragma unroll
        for (int j = 0; j < 8; j++) acc[j] = 0.0f;
        #pragma unroll 4
        for (int c = 6; c < 78; c += 2) {
            float2 v = *reinterpret_cast<const float2*>(R + c);
            #pragma unroll
            for (int j = 0; j < 8; j++) {
                float2 pv = *reinterpret_cast<const float2*>(P0 + j * 78 + c);
                acc[j] += fabsf(v.x - pv.x) + fabsf(v.y - pv.y);
            }
        }
    }

    // per-prior: compute {Pv, l1}, accumulate tile sums {d2, dxy2, t2, liou}
    #pragma unroll
    for (int j = 0; j < 8; j++) {
        float d2 = 0.0f, dxy2 = 0.0f, t2 = 0.0f, li = 0.0f;
        if (act) {
            const float* Pj = P0 + j * 78;
            float dx = v23.y - Pj[3];
            float dy = v45.x - Pj[4];
            dxy2 = dx * dx + dy * dy;
            float th = v45.y - Pj[5];
            t2 = th * th;
            float l1 = acc[j];
            float dis = l1 * (1.0f / 72.0f);
            d2 = dis * dis;
            // liou = 2*l1/(2160+l1): poly approx of 1/(1+u), u = l1/2160 (for k-sum only)
            float u = l1 * (1.0f / 2160.0f);
            li = 2.0f * l1 * (1.0f / 2160.0f) * (1.0f - u * (1.0f - u * (1.0f - u)));
            g_PL[(long long)(b * 16 + pg * 8 + j) * 1000 + row] =
                make_float2(d2 * dxy2 * t2, l1);
        }
        for (int o = 16; o; o >>= 1) {
            d2   += __shfl_xor_sync(FULLM, d2,   o);
            dxy2 += __shfl_xor_sync(FULLM, dxy2, o);
            t2   += __shfl_xor_sync(FULLM, t2,   o);
            li   += __shfl_xor_sync(FULLM, li,   o);
        }
        if (lane == 0) {
            sW[w][j*4+0] = d2; sW[w][j*4+1] = dxy2;
            sW[w][j*4+2] = t2; sW[w][j*4+3] = li;
        }
    }

    if (pg == 0) {
        for (int o = 16; o; o >>= 1) {
            e0 += __shfl_xor_sync(FULLM, e0, o);
            e1 += __shfl_xor_sync(FULLM, e1, o);
        }
        if (lane == 0) { sE[w] = e0; sE[w + 4] = e1; }
    }
    __syncthreads();

    if (tid < 64) {
        int p = tid >> 2, c = tid & 3, j = p & 7;
        int wb = (p >= 8) ? 4 : 0;
        float s = sW[wb][j*4+c] + sW[wb+1][j*4+c] + sW[wb+2][j*4+c] + sW[wb+3][j*4+c];
        ((float*)g_psum)[(((b * 16 + p) * 8) + tile) * 4 + c] = s;
    }
    if (tid == 0) {
        g_Zp[b][tile][0] = sE[0] + sE[1] + sE[2] + sE[3];
        g_Zp[b][tile][1] = sE[4] + sE[5] + sE[6] + sE[7];
    }
}

// ---------------------------------------------------------------------------
// Kernel 2: per-(batch,lane) cost keys, 4-pass radix top-k set selection,
// masked tails, folded final reduce. grid = 1024 blocks, 128 threads.
// ---------------------------------------------------------------------------
__global__ __launch_bounds__(128) void k_sel(const float* __restrict__ OUT,
                                             const float* __restrict__ LAB,
                                             float* __restrict__ out)
{
    const int bid = blockIdx.x;
    const int b = bid >> 4;
    const float* F  = OUT + (long long)b * 78000;
    const float* PR = LAB + (long long)bid * 78;

    __shared__ unsigned sKey[1000];
    __shared__ int      sHist[2][256];
    __shared__ float    sRed[32];
    __shared__ float    sB[12];        // 0:cscale 1:lnZ0 2:iZ0 3:lnZ1 4:iZ1 5..: norms
    __shared__ int      sKk;
    __shared__ unsigned sPfxS;
    __shared__ int      sKkS, sCLS, sCES;
    __shared__ bool     sLast;

    const int tid = threadIdx.x, w = tid >> 5, lane = tid & 31;

    // phase 0: warp-parallel preliminaries (Z, cscale, k, hist zero) — 1 barrier
    if (w == 0) {
        float z = 0.0f;
        if (lane < 8)       z = g_Zp[b][lane][0];
        else if (lane < 16) z = g_Zp[b][lane - 8][1];
        z += __shfl_xor_sync(FULLM, z, 4);
        z += __shfl_xor_sync(FULLM, z, 2);
        z += __shfl_xor_sync(FULLM, z, 1);
        if (lane == 0) { sB[1] = logf(z); sB[2] = 1.0f / z; }
        if (lane == 8) { sB[3] = logf(z); sB[4] = 1.0f / z; }
    } else if (w == 1) {
        float4 p4 = make_float4(0.0f, 0.0f, 0.0f, 0.0f);
        if (lane < 8) p4 = g_psum[bid * 8 + lane];
        #pragma unroll
        for (int o = 4; o; o >>= 1) {
            p4.x += __shfl_xor_sync(FULLM, p4.x, o);
            p4.y += __shfl_xor_sync(FULLM, p4.y, o);
            p4.z += __shfl_xor_sync(FULLM, p4.z, o);
            p4.w += __shfl_xor_sync(FULLM, p4.w, o);
        }
        if (lane == 0) {
            float nd = fmaxf(sqrtf(p4.x), 1e-12f);
            float nx = fmaxf(sqrtf(p4.y), 1e-12f);
            float nt = fmaxf(sqrtf(p4.z), 1e-12f);
            float den = nd * nx * nt;
            sB[0] = 3.0f / (den * den);        // W_SIM / (Nd*Nxy*Nth)^2
            int k = (int)p4.w;
            if (k < 1) k = 1;
            if (k > 64) k = 64;
            sKk = k;
            sPfxS = 0u; sCLS = 0; sKkS = k; sCES = 0;
        }
    } else {
        for (int j = tid - 64; j < 512; j += 64) ((int*)sHist)[j] = 0;
    }
    __syncthreads();

    const float cscale = sB[0];
    const float lnZ0 = sB[1], iZ0 = sB[2], lnZ1 = sB[3], iZ1 = sB[4];
    const int   k = sKk;
    const float pr0 = PR[0], pr1 = PR[1];
    const int nr = (tid < 104) ? 8 : 7;     // 104*8 + 24*7 = 1000

    // phase 1: compute final order-preserving keys directly
    unsigned kr[8];
    float l1r[8];
    #pragma unroll
    for (int rr = 0; rr < 8; rr++) {
        kr[rr] = 0xFFFFFFFFu; l1r[rr] = 0.0f;
        if (rr < nr) {
            int i = tid + rr * 128;
            float2 st = g_PL[(long long)bid * 1000 + i];
            float4 ve = g_v01e[b * 1000 + i];
            float s0 = ve.z * iZ0, s1 = ve.w * iZ1;
            float a0 = (1.0f - s0); a0 = a0 * a0 * (ve.x - lnZ0);
            float a1 = (1.0f - s1); a1 = a1 * a1 * (ve.y - lnZ1);
            float cost = cscale * st.x + a0 * pr0 + a1 * pr1;   // W_CLS = 1
            unsigned u = __float_as_uint(cost);
            u = (u & 0x80000000u) ? ~u : (u | 0x80000000u);
            kr[rr] = u;
            sKey[i] = u;
            l1r[rr] = st.y;
        }
    }

    // 4-pass radix select (MSB first): exact k-th smallest key + CL/CE
    #pragma unroll
    for (int p = 0; p < 4; p++) {
        const int shift = 24 - 8 * p;
        const int buf = p & 1;
        const unsigned pfx = sPfxS;
        #pragma unroll
        for (int rr = 0; rr < 8; rr++) {
            if (rr < nr) {
                bool match = (p == 0) || (((kr[rr] ^ pfx) >> (shift + 8)) == 0u);
                if (match) atomicAdd(&sHist[buf][(kr[rr] >> shift) & 255u], 1);
            }
        }
        __syncthreads();
        if (w == 0) {
            int hv[8]; int local = 0;
            #pragma unroll
            for (int j = 0; j < 8; j++) { hv[j] = sHist[buf][lane * 8 + j]; local += hv[j]; }
            int inc = local;
            #pragma unroll
            for (int o = 1; o < 32; o <<= 1) {
                int t = __shfl_up_sync(FULLM, inc, o);
                if (lane >= o) inc += t;
            }
            const int cumb = inc - local;
            const int kk = sKkS;
            unsigned ball = __ballot_sync(FULLM, inc >= kk);
            int sel_lane = __ffs(ball) - 1;
            if (lane == sel_lane) {
                int run = cumb;
                #pragma unroll
                for (int j = 0; j < 8; j++) {
                    int h = hv[j];
                    if (run + h >= kk) {
                        sPfxS = pfx | ((unsigned)(lane * 8 + j) << shift);
                        sKkS  = kk - run;
                        sCLS += run;
                        sCES  = h;
                        break;
                    }
                    run += h;
                }
            }
        } else {
            for (int j = tid - 32; j < 256; j += 96) sHist[buf ^ 1][j] = 0;
        }
        __syncthreads();
    }
    const unsigned Tkey = sPfxS;
    const int CL = sCLS, CE = sCES;
    const int  m    = k - CL;
    const bool easy = (CE == m);

    // pass A: select + accumulate col sums, focal, liou over selected rows
    const int tgt = (pr0 >= pr1) ? 0 : 1;
    float sq0=0, sq1=0, sq2=0, sq3=0, sfl=0, sll=0;
    int selMask = 0;
    #pragma unroll
    for (int rr = 0; rr < 8; rr++) {
        if (rr >= nr) continue;
        int i = tid + rr * 128;
        bool s;
        if (kr[rr] < Tkey) s = true;
        else if (kr[rr] == Tkey) {
            if (easy) s = true;
            else {
                int rank = 0;
                for (int j = 0; j < i; j++) rank += (sKey[j] == Tkey) ? 1 : 0;
                s = (rank < m);
            }
        } else s = false;
        if (s) {
            selMask |= (1 << rr);
            const float* R = F + i * 78;
            float2 v23 = *reinterpret_cast<const float2*>(R + 2);
            float2 v45 = *reinterpret_cast<const float2*>(R + 4);
            sq0 += v23.x * v23.x;  sq1 += v23.y * v23.y;
            sq2 += v45.x * v45.x;  sq3 += v45.y * v45.y;
            float4 ve = g_v01e[b * 1000 + i];
            float at = (tgt == 0) ? ve.x : ve.y;
            float ao = (tgt == 0) ? ve.y : ve.x;
            float e  = expf(ao - at);
            float lp = -log1pf(e);
            float pt = expf(lp);
            float om = 1.0f - pt;
            sfl += -om * om * lp;
            float l1 = l1r[rr];
            sll += 1.0f - __fdividef(2160.0f - l1, 2160.0f + l1 + 1e-9f);
        }
    }
    for (int o = 16; o; o >>= 1) {
        sq0 += __shfl_xor_sync(FULLM, sq0, o);
        sq1 += __shfl_xor_sync(FULLM, sq1, o);
        sq2 += __shfl_xor_sync(FULLM, sq2, o);
        sq3 += __shfl_xor_sync(FULLM, sq3, o);
        sfl += __shfl_xor_sync(FULLM, sfl, o);
        sll += __shfl_xor_sync(FULLM, sll, o);
    }
    if (lane == 0) {
        float* p2 = &sRed[w * 6];
        p2[0]=sq0; p2[1]=sq1; p2[2]=sq2; p2[3]=sq3; p2[4]=sfl; p2[5]=sll;
    }
    __syncthreads();
    if (tid == 0) {
        float q0=0,q1=0,q2=0,q3=0,FLs=0,LLs=0;
        for (int j = 0; j < 4; j++) {
            q0 += sRed[j*6];   q1 += sRed[j*6+1]; q2 += sRed[j*6+2];
            q3 += sRed[j*6+3]; FLs += sRed[j*6+4]; LLs += sRed[j*6+5];
        }
        float kf = (float)k;
        float lb0 = PR[2], lb1 = PR[3], lb2 = PR[4], lb3 = PR[5];
        float dn0 = fmaxf(sqrtf(q0 + lb0*lb0), 1e-12f);
        float dn1 = fmaxf(sqrtf(q1 + lb1*lb1), 1e-12f);
        float dn2 = fmaxf(sqrtf(q2 + lb2*lb2), 1e-12f);
        float dn3 = fmaxf(sqrtf(q3 + lb3*lb3), 1e-12f);
        sB[1] = 1.0f/dn0; sB[2] = 1.0f/dn1; sB[3] = 1.0f/dn2; sB[4] = 1.0f/dn3;
        sB[5] = lb0/dn0;  sB[6] = lb1/dn1;  sB[7] = lb2/dn2;  sB[8] = lb3/dn3;
        sB[9]  = FLs / kf;
        sB[10] = LLs / kf;
    }
    __syncthreads();

    // pass B: smooth-L1 over selected rows using finalized column norms
    const float i0v = sB[1], i1v = sB[2], i2v = sB[3], i3v = sB[4];
    const float b0v = sB[5], b1v = sB[6], b2v = sB[7], b3v = sB[8];
    float ssl = 0.0f;
    #pragma unroll
    for (int rr = 0; rr < 8; rr++) {
        if (!(selMask & (1 << rr))) continue;
        const float* R = F + (tid + rr * 128) * 78;
        float2 v23 = *reinterpret_cast<const float2*>(R + 2);
        float2 v45 = *reinterpret_cast<const float2*>(R + 4);
        float h = 0.0f, d, ad;
        d = v23.x * i0v - b0v; ad = fabsf(d); h += (ad < 1.0f) ? 0.5f*d*d : ad - 0.5f;
        d = v23.y * i1v - b1v; ad = fabsf(d); h += (ad < 1.0f) ? 0.5f*d*d : ad - 0.5f;
        d = v45.x * i2v - b2v; ad = fabsf(d); h += (ad < 1.0f) ? 0.5f*d*d : ad - 0.5f;
        d = v45.y * i3v - b3v; ad = fabsf(d); h += (ad < 1.0f) ? 0.5f*d*d : ad - 0.5f;
        ssl += 0.25f * h;
    }
    for (int o = 16; o; o >>= 1) ssl += __shfl_xor_sync(FULLM, ssl, o);
    if (lane == 0) sRed[w] = ssl;
    __syncthreads();
    if (tid == 0) {
        float SSL = sRed[0] + sRed[1] + sRed[2] + sRed[3];
        g_res[bid*3 + 0] = SSL / (float)k;
        g_res[bid*3 + 1] = sB[10];
        g_res[bid*3 + 2] = sB[9];
    }
    __syncthreads();

    // ---- folded final reduction: last block to finish combines everything ---
    __threadfence();
    if (tid == 0) {
        unsigned t = atomicAdd(&g_done, 1u);
        sLast = (t == (unsigned)(gridDim.x - 1));
    }
    __syncthreads();
    if (!sLast) return;
    __threadfence();

    float a = 0.0f, bb = 0.0f, cc = 0.0f;
    for (int i = tid; i < 1024; i += 128) {
        a  += g_res[i*3];
        bb += g_res[i*3+1];
        cc += g_res[i*3+2];
    }
    for (int o = 16; o; o >>= 1) {
        a  += __shfl_xor_sync(FULLM, a,  o);
        bb += __shfl_xor_sync(FULLM, bb, o);
        cc += __shfl_xor_sync(FULLM, cc, o);
    }
    if (lane == 0) { sRed[w] = a; sRed[w+8] = bb; sRed[w+16] = cc; }
    __syncthreads();
    if (tid == 0) {
        float A = sRed[0]+sRed[1]+sRed[2]+sRed[3];
        float B = sRed[8]+sRed[9]+sRed[10]+sRed[11];
        float C = sRed[16]+sRed[17]+sRed[18]+sRed[19];
        float sl = A * (1.0f/1024.0f);
        float ll = B * (1.0f/1024.0f);
        float fl = C * (1.0f/1024.0f);
        float loss = (sl > 0.0f ? 0.5f*sl : 0.0f)
                   + (ll > 0.0f ? 2.0f*ll : 0.0f)
                   + (fl > 0.0f ? 2.0f*fl : 0.0f);
        out[0] = loss;
        g_done = 0;                      // reset for next graph replay
    }
}

extern "C" void kernel_launch(void* const* d_in, const int* in_sizes, int n_in,
                              void* d_out, int out_size)
{
    const float* outp = (const float*)d_in[0];
    const float* lab  = (const float*)d_in[1];
    if (n_in >= 2 && in_sizes[0] == 64*16*78) {   // defensive: metadata order
        outp = (const float*)d_in[1];
        lab  = (const float*)d_in[0];
    }
    k_stats<<<dim3(64, 8), 256>>>(outp, lab);
    k_sel  <<<1024, 128>>>(outp, lab, (float*)d_out);
}